// round 2
// baseline (speedup 1.0000x reference)
#include <cuda_runtime.h>
#include <cuda_bf16.h>

#define L    2048
#define D    64
#define QPB  32          // queries per block
#define TPQ  4           // threads per query (16 dims each)
#define NT   (QPB*TPQ)   // 128 threads
#define TK   64          // key tile
#define CH   16          // softmax chunk
#define DS   (D/TPQ)     // 16 dims per thread

using u64 = unsigned long long;

__device__ __forceinline__ u64 pack2(float lo, float hi) {
    u64 r; asm("mov.b64 %0, {%1, %2};" : "=l"(r) : "f"(lo), "f"(hi)); return r;
}
__device__ __forceinline__ void unpack2(u64 v, float &lo, float &hi) {
    asm("mov.b64 {%0, %1}, %2;" : "=f"(lo), "=f"(hi) : "l"(v));
}
__device__ __forceinline__ void fma2(u64 &d, u64 a, u64 b) {
    asm("fma.rn.f32x2 %0, %1, %2, %0;" : "+l"(d) : "l"(a), "l"(b));
}
__device__ __forceinline__ void mul2(u64 &d, u64 a) {
    asm("mul.rn.f32x2 %0, %0, %1;" : "+l"(d) : "l"(a));
}
__device__ __forceinline__ u64 add2(u64 a, u64 b) {
    u64 r; asm("add.rn.f32x2 %0, %1, %2;" : "=l"(r) : "l"(a), "l"(b)); return r;
}

__global__ void __launch_bounds__(NT, 4)
attn_split4_kernel(const float* __restrict__ Q,
                   const float* __restrict__ K,
                   const float* __restrict__ V,
                   float* __restrict__ O)
{
    __shared__ float Ks[TK * D];
    __shared__ float Vs[TK * D];

    const int tid   = threadIdx.x;
    const int b     = blockIdx.y;
    const int q     = blockIdx.x * QPB + (tid >> 2);  // query row
    const int lane4 = tid & 3;                         // dim-slice id
    const int doff  = lane4 * DS;                      // dim offset (16-float slice)
    const float scale = 0.125f;                        // 1/sqrt(64)

    // Load this thread's 16-dim query slice, pre-scaled.
    const float* qp = Q + ((size_t)b * L + q) * D + doff;
    u64 qv[DS / 2];
#pragma unroll
    for (int i = 0; i < DS / 4; i++) {
        float4 t = reinterpret_cast<const float4*>(qp)[i];
        qv[2 * i]     = pack2(t.x * scale, t.y * scale);
        qv[2 * i + 1] = pack2(t.z * scale, t.w * scale);
    }

    u64 acc[DS / 2];
#pragma unroll
    for (int i = 0; i < DS / 2; i++) acc[i] = 0ull;

    float m = -1e30f;
    float l = 0.f;

    const float4* Kg = reinterpret_cast<const float4*>(K + (size_t)b * L * D);
    const float4* Vg = reinterpret_cast<const float4*>(V + (size_t)b * L * D);
    float4* Ks4 = reinterpret_cast<float4*>(Ks);
    float4* Vs4 = reinterpret_cast<float4*>(Vs);

#pragma unroll 1
    for (int kt = 0; kt < L; kt += TK) {
        __syncthreads();
        const int base = kt * (D / 4);
#pragma unroll
        for (int i = 0; i < (TK * D / 4) / NT; i++) {   // 8 float4 each
            Ks4[tid + i * NT] = Kg[base + tid + i * NT];
            Vs4[tid + i * NT] = Vg[base + tid + i * NT];
        }
        __syncthreads();

#pragma unroll 1
        for (int j0 = 0; j0 < TK; j0 += CH) {
            float s[CH];
#pragma unroll
            for (int jj = 0; jj < CH; jj++) {
                const u64* kr = reinterpret_cast<const u64*>(Ks + (j0 + jj) * D + doff);
                u64 a0 = 0ull, a1 = 0ull, a2 = 0ull, a3 = 0ull;
                fma2(a0, qv[0], kr[0]);
                fma2(a1, qv[1], kr[1]);
                fma2(a2, qv[2], kr[2]);
                fma2(a3, qv[3], kr[3]);
                fma2(a0, qv[4], kr[4]);
                fma2(a1, qv[5], kr[5]);
                fma2(a2, qv[6], kr[6]);
                fma2(a3, qv[7], kr[7]);
                u64 a01 = add2(a0, a1), a23 = add2(a2, a3);
                u64 at  = add2(a01, a23);
                float lo, hi; unpack2(at, lo, hi);
                float sum = lo + hi;
                // butterfly reduce across the 4 lanes owning this query
                sum += __shfl_xor_sync(0xFFFFFFFFu, sum, 1);
                sum += __shfl_xor_sync(0xFFFFFFFFu, sum, 2);
                s[jj] = sum;
            }
            // online softmax: one rescale per chunk
            float cmax = s[0];
#pragma unroll
            for (int jj = 1; jj < CH; jj++) cmax = fmaxf(cmax, s[jj]);
            float mnew = fmaxf(m, cmax);
            float corr = __expf(m - mnew);
            m = mnew;
            l *= corr;
            u64 corr2 = pack2(corr, corr);
#pragma unroll
            for (int i = 0; i < DS / 2; i++) mul2(acc[i], corr2);
#pragma unroll
            for (int jj = 0; jj < CH; jj++) {
                float p = __expf(s[jj] - m);
                l += p;
                u64 p2 = pack2(p, p);
                const u64* vr = reinterpret_cast<const u64*>(Vs + (j0 + jj) * D + doff);
#pragma unroll
                for (int i = 0; i < DS / 2; i++) fma2(acc[i], p2, vr[i]);
            }
        }
    }

    const float inv = 1.f / l;
    float* op = O + ((size_t)b * L + q) * D + doff;
#pragma unroll
    for (int i = 0; i < DS / 4; i++) {
        float x0, x1, x2, x3;
        unpack2(acc[2 * i],     x0, x1);
        unpack2(acc[2 * i + 1], x2, x3);
        reinterpret_cast<float4*>(op)[i] =
            make_float4(x0 * inv, x1 * inv, x2 * inv, x3 * inv);
    }
}

extern "C" void kernel_launch(void* const* d_in, const int* in_sizes, int n_in,
                              void* d_out, int out_size)
{
    const float* Q = (const float*)d_in[0];
    const float* K = (const float*)d_in[1];
    const float* V = (const float*)d_in[2];
    float* O = (float*)d_out;

    const int B = in_sizes[0] / (L * D);   // 8
    dim3 grid(L / QPB, B);                 // 64 x 8 = 512 blocks
    attn_split4_kernel<<<grid, NT>>>(Q, K, V, O);
}

// round 3
// speedup vs baseline: 2.7696x; 2.7696x over previous
#include <cuda_runtime.h>
#include <cuda_bf16.h>

#define BB    8
#define L     2048
#define D     64
#define BQ    64            // queries per block == threads
#define TK    64            // key tile in smem
#define CH    16            // softmax chunk
#define SPLIT 8
#define KPS   (L / SPLIT)   // 256 keys per split

using u64 = unsigned long long;

// split-K scratch (static device arrays; no allocation)
__device__ float g_acc[(size_t)BB * L * SPLIT * D];   // 32 MB
__device__ float g_m[BB * L * SPLIT];
__device__ float g_l[BB * L * SPLIT];

__device__ __forceinline__ u64 pack2(float lo, float hi) {
    u64 r; asm("mov.b64 %0, {%1, %2};" : "=l"(r) : "f"(lo), "f"(hi)); return r;
}
__device__ __forceinline__ void unpack2(u64 v, float &lo, float &hi) {
    asm("mov.b64 {%0, %1}, %2;" : "=f"(lo), "=f"(hi) : "l"(v));
}
__device__ __forceinline__ void fma2(u64 &d, u64 a, u64 b) {
    asm("fma.rn.f32x2 %0, %1, %2, %0;" : "+l"(d) : "l"(a), "l"(b));
}
__device__ __forceinline__ void mul2(u64 &d, u64 a) {
    asm("mul.rn.f32x2 %0, %0, %1;" : "+l"(d) : "l"(a));
}
__device__ __forceinline__ u64 add2(u64 a, u64 b) {
    u64 r; asm("add.rn.f32x2 %0, %1, %2;" : "=l"(r) : "l"(a), "l"(b)); return r;
}
// one LDS.128: two u64 halves of a 16-byte shared read
__device__ __forceinline__ void lds2(const float* p, u64 &a, u64 &b) {
    unsigned s = (unsigned)__cvta_generic_to_shared(p);
    asm volatile("ld.shared.v2.b64 {%0, %1}, [%2];" : "=l"(a), "=l"(b) : "r"(s));
}

__global__ void __launch_bounds__(BQ, 5)
attn_splitk_kernel(const float* __restrict__ Q,
                   const float* __restrict__ K,
                   const float* __restrict__ V)
{
    __shared__ float Ks[TK * D];
    __shared__ float Vs[TK * D];

    const int tid = threadIdx.x;
    const int b   = blockIdx.y;
    const int sp  = blockIdx.z;
    const int qi  = blockIdx.x * BQ + tid;
    const float scale = 0.125f;              // 1/sqrt(64)

    // query row, pre-scaled, packed
    const float* qp = Q + ((size_t)b * L + qi) * D;
    u64 qv[D / 2];
#pragma unroll
    for (int i = 0; i < D / 4; i++) {
        float4 t = reinterpret_cast<const float4*>(qp)[i];
        qv[2 * i]     = pack2(t.x * scale, t.y * scale);
        qv[2 * i + 1] = pack2(t.z * scale, t.w * scale);
    }

    u64 acc[D / 2];
#pragma unroll
    for (int i = 0; i < D / 2; i++) acc[i] = 0ull;
    float m = -1e30f, l = 0.f;

    const int k0 = sp * KPS;
    const float4* Kg = reinterpret_cast<const float4*>(K + (size_t)b * L * D);
    const float4* Vg = reinterpret_cast<const float4*>(V + (size_t)b * L * D);
    float4* Ks4 = reinterpret_cast<float4*>(Ks);
    float4* Vs4 = reinterpret_cast<float4*>(Vs);

#pragma unroll 1
    for (int kt = k0; kt < k0 + KPS; kt += TK) {
        __syncthreads();
        const int base = kt * (D / 4);
#pragma unroll
        for (int i = 0; i < (TK * D / 4) / BQ; i++) {   // 16 float4 each
            Ks4[tid + i * BQ] = Kg[base + tid + i * BQ];
            Vs4[tid + i * BQ] = Vg[base + tid + i * BQ];
        }
        __syncthreads();

#pragma unroll 1
        for (int j0 = 0; j0 < TK; j0 += CH) {
            float s[CH];
#pragma unroll
            for (int jj = 0; jj < CH; jj++) {
                const float* kr = Ks + (j0 + jj) * D;
                u64 a0 = 0ull, a1 = 0ull, a2 = 0ull, a3 = 0ull;
#pragma unroll
                for (int i = 0; i < 8; i++) {           // 8 × LDS.128 per half
                    u64 x, y;
                    lds2(kr + 8 * i,     x, y);
                    fma2(a0, qv[4 * i],     x);
                    fma2(a1, qv[4 * i + 1], y);
                    lds2(kr + 8 * i + 4, x, y);
                    fma2(a2, qv[4 * i + 2], x);
                    fma2(a3, qv[4 * i + 3], y);
                }
                u64 at = add2(add2(a0, a1), add2(a2, a3));
                float lo, hi; unpack2(at, lo, hi);
                s[jj] = lo + hi;
            }
            float cmax = s[0];
#pragma unroll
            for (int jj = 1; jj < CH; jj++) cmax = fmaxf(cmax, s[jj]);
            float mnew = fmaxf(m, cmax);
            float corr = __expf(m - mnew);
            m = mnew;
            l *= corr;
            u64 corr2 = pack2(corr, corr);
#pragma unroll
            for (int i = 0; i < D / 2; i++) mul2(acc[i], corr2);
#pragma unroll
            for (int jj = 0; jj < CH; jj++) {
                float p = __expf(s[jj] - m);
                l += p;
                u64 p2 = pack2(p, p);
                const float* vr = Vs + (j0 + jj) * D;
#pragma unroll
                for (int i = 0; i < 16; i++) {
                    u64 x, y;
                    lds2(vr + 4 * i, x, y);
                    fma2(acc[2 * i],     p2, x);
                    fma2(acc[2 * i + 1], p2, y);
                }
            }
        }
    }

    // write partials (unnormalized)
    const size_t pi = ((size_t)b * L + qi) * SPLIT + sp;
    g_m[pi] = m;
    g_l[pi] = l;
    float* ap = g_acc + pi * D;
#pragma unroll
    for (int i = 0; i < D / 4; i++) {
        float x0, x1, x2, x3;
        unpack2(acc[2 * i],     x0, x1);
        unpack2(acc[2 * i + 1], x2, x3);
        reinterpret_cast<float4*>(ap)[i] = make_float4(x0, x1, x2, x3);
    }
}

__global__ void __launch_bounds__(256)
attn_combine_kernel(float* __restrict__ O)
{
    const int idx = blockIdx.x * blockDim.x + threadIdx.x;   // b*L + q
    if (idx >= BB * L) return;

    float mv[SPLIT], lv[SPLIT];
    float M = -1e30f;
#pragma unroll
    for (int s = 0; s < SPLIT; s++) {
        mv[s] = g_m[(size_t)idx * SPLIT + s];
        lv[s] = g_l[(size_t)idx * SPLIT + s];
        M = fmaxf(M, mv[s]);
    }
    float w[SPLIT], Lsum = 0.f;
#pragma unroll
    for (int s = 0; s < SPLIT; s++) {
        w[s] = __expf(mv[s] - M);
        Lsum += w[s] * lv[s];
    }
    const float inv = 1.f / Lsum;

    float out[D];
#pragma unroll
    for (int d = 0; d < D; d++) out[d] = 0.f;
#pragma unroll
    for (int s = 0; s < SPLIT; s++) {
        const float4* ap = reinterpret_cast<const float4*>(
            g_acc + ((size_t)idx * SPLIT + s) * D);
        const float ws = w[s];
#pragma unroll
        for (int i = 0; i < D / 4; i++) {
            float4 t = ap[i];
            out[4 * i]     += ws * t.x;
            out[4 * i + 1] += ws * t.y;
            out[4 * i + 2] += ws * t.z;
            out[4 * i + 3] += ws * t.w;
        }
    }
    float4* op = reinterpret_cast<float4*>(O + (size_t)idx * D);
#pragma unroll
    for (int i = 0; i < D / 4; i++)
        op[i] = make_float4(out[4 * i] * inv, out[4 * i + 1] * inv,
                            out[4 * i + 2] * inv, out[4 * i + 3] * inv);
}

extern "C" void kernel_launch(void* const* d_in, const int* in_sizes, int n_in,
                              void* d_out, int out_size)
{
    const float* Q = (const float*)d_in[0];
    const float* K = (const float*)d_in[1];
    const float* V = (const float*)d_in[2];
    float* O = (float*)d_out;

    dim3 grid(L / BQ, BB, SPLIT);            // 32 x 8 x 8 = 2048 blocks
    attn_splitk_kernel<<<grid, BQ>>>(Q, K, V);
    attn_combine_kernel<<<(BB * L + 255) / 256, 256>>>(O);
}

// round 5
// speedup vs baseline: 11.9440x; 4.3125x over previous
#include <cuda_runtime.h>
#include <cuda_bf16.h>
#include <cstdint>

#define BB 8
#define L  2048
#define D  64
#define TM 64               // queries per CTA (4 warps x 16)
#define TN 64               // keys per tile
#define NTILES (L / TN)     // 32
#define NT 128
#define SST 144             // padded smem row stride in bytes (72 bf16)

// bf16 hi/lo operands (static device scratch)
__device__ __nv_bfloat16 gQhi[BB * L * D], gQlo[BB * L * D];
__device__ __nv_bfloat16 gKhi[BB * L * D], gKlo[BB * L * D];
__device__ __nv_bfloat16 gVhi[BB * L * D], gVlo[BB * L * D];

// smem region byte offsets (each 64 rows x 144B = 9216B)
#define SQH 0
#define SQL 9216
#define SKH 18432
#define SKL 27648
#define SVH 36864
#define SVL 46080
#define SMEM_TOTAL 55296

__device__ __forceinline__ uint32_t smem_u32(const void* p) {
    uint32_t a;
    asm("{ .reg .u64 t; cvta.to.shared.u64 t, %1; cvt.u32.u64 %0, t; }" : "=r"(a) : "l"(p));
    return a;
}
__device__ __forceinline__ void ldsm4(uint32_t r[4], uint32_t a) {
    asm volatile("ldmatrix.sync.aligned.m8n8.x4.shared.b16 {%0,%1,%2,%3}, [%4];"
                 : "=r"(r[0]), "=r"(r[1]), "=r"(r[2]), "=r"(r[3]) : "r"(a));
}
__device__ __forceinline__ void ldsm4t(uint32_t r[4], uint32_t a) {
    asm volatile("ldmatrix.sync.aligned.m8n8.x4.trans.shared.b16 {%0,%1,%2,%3}, [%4];"
                 : "=r"(r[0]), "=r"(r[1]), "=r"(r[2]), "=r"(r[3]) : "r"(a));
}
// D += A * B  (m16n8k16, bf16 in, fp32 acc)
__device__ __forceinline__ void mma(float d[4], const uint32_t a[4],
                                    uint32_t b0, uint32_t b1) {
    asm volatile("mma.sync.aligned.m16n8k16.row.col.f32.bf16.bf16.f32 "
                 "{%0,%1,%2,%3}, {%4,%5,%6,%7}, {%8,%9}, {%0,%1,%2,%3};"
                 : "+f"(d[0]), "+f"(d[1]), "+f"(d[2]), "+f"(d[3])
                 : "r"(a[0]), "r"(a[1]), "r"(a[2]), "r"(a[3]), "r"(b0), "r"(b1));
}
// (x,y) -> bf16x2 hi + bf16x2 lo residual
__device__ __forceinline__ void packhl(float x, float y, uint32_t &h, uint32_t &lo) {
    __nv_bfloat162 hh = __floats2bfloat162_rn(x, y);
    __nv_bfloat162 ll = __floats2bfloat162_rn(x - __bfloat162float(hh.x),
                                              y - __bfloat162float(hh.y));
    h  = *reinterpret_cast<uint32_t*>(&hh);
    lo = *reinterpret_cast<uint32_t*>(&ll);
}

// ---------------- pre-convert: fp32 -> bf16 hi/lo ---------------------------
__global__ void __launch_bounds__(256)
convert_kernel(const float* __restrict__ Q, const float* __restrict__ K,
               const float* __restrict__ V)
{
    const int i = blockIdx.x * 256 + threadIdx.x;
    if (i >= BB * L * D) return;
    float q = Q[i] * 0.125f;                    // fold 1/sqrt(64)
    __nv_bfloat16 qh = __float2bfloat16(q);
    gQhi[i] = qh; gQlo[i] = __float2bfloat16(q - __bfloat162float(qh));
    float k = K[i];
    __nv_bfloat16 kh = __float2bfloat16(k);
    gKhi[i] = kh; gKlo[i] = __float2bfloat16(k - __bfloat162float(kh));
    float v = V[i];
    __nv_bfloat16 vh = __float2bfloat16(v);
    gVhi[i] = vh; gVlo[i] = __float2bfloat16(v - __bfloat162float(vh));
}

// ---------------- main kernel ------------------------------------------------
__global__ void __launch_bounds__(NT, 3)
attn_hmma_kernel(float* __restrict__ Og)
{
    extern __shared__ char sm[];
    const uint32_t sb = smem_u32(sm);
    const int tid  = threadIdx.x;
    const int lane = tid & 31;
    const int w    = tid >> 5;          // warp 0..3
    const int g    = lane >> 2;         // group 0..7
    const int t4   = lane & 3;
    const int b    = blockIdx.y;
    const int q0   = blockIdx.x * TM;

    // ---- stage Q hi/lo into padded smem ----
    {
        const uint4* qh = reinterpret_cast<const uint4*>(gQhi + ((size_t)b * L + q0) * D);
        const uint4* ql = reinterpret_cast<const uint4*>(gQlo + ((size_t)b * L + q0) * D);
#pragma unroll
        for (int i = tid; i < TM * 8; i += NT) {
            int r = i >> 3, c = i & 7;
            uint32_t so = r * SST + c * 16;
            *reinterpret_cast<uint4*>(sm + SQH + so) = qh[i];
            *reinterpret_cast<uint4*>(sm + SQL + so) = ql[i];
        }
    }
    __syncthreads();

    // ---- Q fragments (A of m16n8k16), held in registers for all tiles ----
    uint32_t qhf[4][4], qlf[4][4];
    {
        const int row = 16 * w + (lane & 7) + ((lane >> 3) & 1) * 8;
        const int kb  = (lane >> 4) << 4;
#pragma unroll
        for (int s = 0; s < 4; s++) {
            uint32_t a = sb + SQH + row * SST + 32 * s + kb;
            ldsm4(qhf[s], a);
            ldsm4(qlf[s], a + (SQL - SQH));
        }
    }

    float Oa[8][4];
#pragma unroll
    for (int j = 0; j < 8; j++)
#pragma unroll
        for (int i = 0; i < 4; i++) Oa[j][i] = 0.f;
    float m0 = -1e30f, m1 = -1e30f, l0 = 0.f, l1 = 0.f;

    const int k_lr = lane & 7, k_gl = lane >> 3;                    // K ldsm addressing
    const int v_row = (lane & 7) + ((lane >> 3) & 1) * 8;           // V ldsm addressing
    const int v_cb  = (lane >> 4) << 4;

#pragma unroll 1
    for (int kt = 0; kt < NTILES; kt++) {
        __syncthreads();
        // ---- stage K/V hi/lo tile ----
        {
            const size_t gb = ((size_t)b * L + kt * TN) * D;
            const uint4* kh = reinterpret_cast<const uint4*>(gKhi + gb);
            const uint4* kl = reinterpret_cast<const uint4*>(gKlo + gb);
            const uint4* vh = reinterpret_cast<const uint4*>(gVhi + gb);
            const uint4* vl = reinterpret_cast<const uint4*>(gVlo + gb);
#pragma unroll
            for (int i = tid; i < TN * 8; i += NT) {
                int r = i >> 3, c = i & 7;
                uint32_t so = r * SST + c * 16;
                *reinterpret_cast<uint4*>(sm + SKH + so) = kh[i];
                *reinterpret_cast<uint4*>(sm + SKL + so) = kl[i];
                *reinterpret_cast<uint4*>(sm + SVH + so) = vh[i];
                *reinterpret_cast<uint4*>(sm + SVL + so) = vl[i];
            }
        }
        __syncthreads();

        // ---- S = Qhi Khi^T + Qlo Khi^T + Qhi Klo^T ----
        float S[8][4];
#pragma unroll
        for (int j = 0; j < 8; j++) {
#pragma unroll
            for (int i = 0; i < 4; i++) S[j][i] = 0.f;
#pragma unroll
            for (int s2 = 0; s2 < 2; s2++) {
                uint32_t ka = sb + SKH + (8 * j + k_lr) * SST + 64 * s2 + 16 * k_gl;
                uint32_t kh_[4], kl_[4];
                ldsm4(kh_, ka);
                ldsm4(kl_, ka + (SKL - SKH));
                mma(S[j], qhf[2 * s2],     kh_[0], kh_[1]);
                mma(S[j], qhf[2 * s2 + 1], kh_[2], kh_[3]);
                mma(S[j], qlf[2 * s2],     kh_[0], kh_[1]);
                mma(S[j], qlf[2 * s2 + 1], kh_[2], kh_[3]);
                mma(S[j], qhf[2 * s2],     kl_[0], kl_[1]);
                mma(S[j], qhf[2 * s2 + 1], kl_[2], kl_[3]);
            }
        }

        // ---- online softmax (rows g and g+8) ----
        float mx0 = -1e30f, mx1 = -1e30f;
#pragma unroll
        for (int j = 0; j < 8; j++) {
            mx0 = fmaxf(mx0, fmaxf(S[j][0], S[j][1]));
            mx1 = fmaxf(mx1, fmaxf(S[j][2], S[j][3]));
        }
        mx0 = fmaxf(mx0, __shfl_xor_sync(0xffffffffu, mx0, 1));
        mx0 = fmaxf(mx0, __shfl_xor_sync(0xffffffffu, mx0, 2));
        mx1 = fmaxf(mx1, __shfl_xor_sync(0xffffffffu, mx1, 1));
        mx1 = fmaxf(mx1, __shfl_xor_sync(0xffffffffu, mx1, 2));
        const float nm0 = fmaxf(m0, mx0), nm1 = fmaxf(m1, mx1);
        const float c0 = __expf(m0 - nm0), c1 = __expf(m1 - nm1);
        m0 = nm0; m1 = nm1;

        float ps0 = 0.f, ps1 = 0.f;
#pragma unroll
        for (int j = 0; j < 8; j++) {
            S[j][0] = __expf(S[j][0] - m0); S[j][1] = __expf(S[j][1] - m0);
            S[j][2] = __expf(S[j][2] - m1); S[j][3] = __expf(S[j][3] - m1);
            ps0 += S[j][0] + S[j][1];
            ps1 += S[j][2] + S[j][3];
        }
        ps0 += __shfl_xor_sync(0xffffffffu, ps0, 1);
        ps0 += __shfl_xor_sync(0xffffffffu, ps0, 2);
        ps1 += __shfl_xor_sync(0xffffffffu, ps1, 1);
        ps1 += __shfl_xor_sync(0xffffffffu, ps1, 2);
        l0 = l0 * c0 + ps0;
        l1 = l1 * c1 + ps1;

        // rescale O accumulators
#pragma unroll
        for (int j = 0; j < 8; j++) {
            Oa[j][0] *= c0; Oa[j][1] *= c0;
            Oa[j][2] *= c1; Oa[j][3] *= c1;
        }

        // ---- pack P (S-acc fragment == next A fragment) ----
        uint32_t phi[4][4], plo[4][4];
#pragma unroll
        for (int s = 0; s < 4; s++) {
            packhl(S[2 * s][0],     S[2 * s][1],     phi[s][0], plo[s][0]);
            packhl(S[2 * s][2],     S[2 * s][3],     phi[s][1], plo[s][1]);
            packhl(S[2 * s + 1][0], S[2 * s + 1][1], phi[s][2], plo[s][2]);
            packhl(S[2 * s + 1][2], S[2 * s + 1][3], phi[s][3], plo[s][3]);
        }

        // ---- O += Phi Vhi + Plo Vhi + Phi Vlo ----
#pragma unroll
        for (int s = 0; s < 4; s++) {
#pragma unroll
            for (int jp = 0; jp < 4; jp++) {
                uint32_t va = sb + SVH + (16 * s + v_row) * SST + 32 * jp + v_cb;
                uint32_t vh_[4], vl_[4];
                ldsm4t(vh_, va);
                ldsm4t(vl_, va + (SVL - SVH));
                mma(Oa[2 * jp],     phi[s], vh_[0], vh_[1]);
                mma(Oa[2 * jp + 1], phi[s], vh_[2], vh_[3]);
                mma(Oa[2 * jp],     plo[s], vh_[0], vh_[1]);
                mma(Oa[2 * jp + 1], plo[s], vh_[2], vh_[3]);
                mma(Oa[2 * jp],     phi[s], vl_[0], vl_[1]);
                mma(Oa[2 * jp + 1], phi[s], vl_[2], vl_[3]);
            }
        }
    }

    // ---- epilogue ----
    const float i0 = 1.f / l0, i1 = 1.f / l1;
    float* op = Og + ((size_t)b * L + q0 + 16 * w + g) * D;
#pragma unroll
    for (int j = 0; j < 8; j++) {
        *reinterpret_cast<float2*>(op + 8 * j + 2 * t4) =
            make_float2(Oa[j][0] * i0, Oa[j][1] * i0);
        *reinterpret_cast<float2*>(op + 8 * (size_t)D + 8 * j + 2 * t4) =
            make_float2(Oa[j][2] * i1, Oa[j][3] * i1);
    }
}

extern "C" void kernel_launch(void* const* d_in, const int* in_sizes, int n_in,
                              void* d_out, int out_size)
{
    const float* Q = (const float*)d_in[0];
    const float* K = (const float*)d_in[1];
    const float* V = (const float*)d_in[2];
    float* O = (float*)d_out;

    cudaFuncSetAttribute(attn_hmma_kernel,
                         cudaFuncAttributeMaxDynamicSharedMemorySize, SMEM_TOTAL);

    convert_kernel<<<(BB * L * D + 255) / 256, 256>>>(Q, K, V);
    dim3 grid(L / TM, BB);                  // 32 x 8 = 256 CTAs
    attn_hmma_kernel<<<grid, NT, SMEM_TOTAL>>>(O);
}